// round 15
// baseline (speedup 1.0000x reference)
#include <cuda_runtime.h>
#include <cuda_fp16.h>
#include <cstdint>

using f16 = __half;
#define DINLINE __device__ __forceinline__

#define SEQ 128
#define BATCH 32
#define VOCAB 32000
#define HID 1024
#define NLAYER 2
#define M_TOT (SEQ * BATCH)   // 4096
#define GATES (4 * HID)       // 4096

// ---- static device scratch ----
__device__ f16   g_wihH[2ull * GATES * HID];
__device__ f16   g_whhH[2ull * GATES * HID];
__device__ f16   g_wdecH[(size_t)VOCAB * HID];
__device__ float g_biasC[2 * GATES];
__device__ f16   g_xa[(size_t)M_TOT * HID];
__device__ f16   g_xb[(size_t)M_TOT * HID];
__device__ float g_gates[(size_t)M_TOT * GATES];
__device__ f16   g_hbuf[2][BATCH * HID];
__device__ unsigned g_bar_arrive;
__device__ volatile unsigned g_bar_gen;

DINLINE uint32_t smaddr(const void* p) { return (uint32_t)__cvta_generic_to_shared(p); }
DINLINE void ldm4(uint32_t& r0, uint32_t& r1, uint32_t& r2, uint32_t& r3, uint32_t a) {
    asm volatile("ldmatrix.sync.aligned.m8n8.x4.shared.b16 {%0,%1,%2,%3}, [%4];"
                 : "=r"(r0), "=r"(r1), "=r"(r2), "=r"(r3) : "r"(a));
}
DINLINE void mma16816(float* c, uint32_t a0, uint32_t a1, uint32_t a2, uint32_t a3,
                      uint32_t b0, uint32_t b1) {
    asm volatile("mma.sync.aligned.m16n8k16.row.col.f32.f16.f16.f32 "
                 "{%0,%1,%2,%3}, {%4,%5,%6,%7}, {%8,%9}, {%0,%1,%2,%3};"
                 : "+f"(c[0]), "+f"(c[1]), "+f"(c[2]), "+f"(c[3])
                 : "r"(a0), "r"(a1), "r"(a2), "r"(a3), "r"(b0), "r"(b1));
}
DINLINE void cpa16(uint32_t s, const void* g) {
    asm volatile("cp.async.cg.shared.global [%0], [%1], 16;" :: "r"(s), "l"(g));
}
DINLINE void cpa_commit() { asm volatile("cp.async.commit_group;"); }
template <int N> DINLINE void cpa_wait() { asm volatile("cp.async.wait_group %0;" :: "n"(N)); }
DINLINE float sigmf(float x) { return 1.0f / (1.0f + __expf(-x)); }

// ---- fp32 -> fp16 convert ----
__global__ void f2h_k(const float* __restrict__ s, f16* __restrict__ d, long n) {
    long i = ((long)blockIdx.x * blockDim.x + threadIdx.x) * 4;
    long st = (long)gridDim.x * blockDim.x * 4;
    for (; i < n; i += st) {
        float4 v = *(const float4*)(s + i);
        __half2* o = (__half2*)(d + i);
        o[0] = __floats2half2_rn(v.x, v.y);
        o[1] = __floats2half2_rn(v.z, v.w);
    }
}
__global__ void bias_k(const float* __restrict__ a, const float* __restrict__ b,
                       float* __restrict__ o, int n) {
    int i = blockIdx.x * blockDim.x + threadIdx.x;
    if (i < n) o[i] = a[i] + b[i];
}
__global__ void embed_k(const int* __restrict__ tok, const float* __restrict__ emb,
                        f16* __restrict__ x) {
    int m = blockIdx.x;
    const float4* s = (const float4*)(emb + (size_t)tok[m] * HID);
    __half2* o = (__half2*)(x + (size_t)m * HID);
    float4 v = s[threadIdx.x];
    o[threadIdx.x * 2 + 0] = __floats2half2_rn(v.x, v.y);
    o[threadIdx.x * 2 + 1] = __floats2half2_rn(v.z, v.w);
}

// ============================================================================
// NT GEMM v3: C[M,N] = A[M,1024] @ B[N,1024]^T + bias, fp32 out.
// CTA tile 128x256, 8 warps (2m x 4n), warp tile 64x64, BK=64,
// 3-stage cp.async ring. Pitch-72 SMEM rows (144B) -> conflict-free ldmatrix.
// ============================================================================
#define GP 72
#define G_ABYTES (128 * GP * 2)              // 18432
#define G_BBYTES (256 * GP * 2)              // 36864
#define G_STG (G_ABYTES + G_BBYTES)          // 55296
#define GEMM_SMEM (3 * G_STG)                // 165888

__global__ __launch_bounds__(256, 1) void gemm_nt_k(
    const f16* __restrict__ A, const f16* __restrict__ B,
    const float* __restrict__ bias, float* __restrict__ C, long ldc) {
    extern __shared__ __align__(16) char sm[];
    uint32_t sb = smaddr(sm);

    int tid = threadIdx.x, lane = tid & 31, warp = tid >> 5;
    int m0 = blockIdx.y * 128, n0 = blockIdx.x * 256;
    int wm = (warp >> 2) * 64, wn = (warp & 3) * 64;
    int mat = lane >> 3, lr = lane & 7;
    // ldmatrix per-thread offsets (bytes)
    int arow = (mat & 1) * 8 + lr, acol = (mat >> 1) * 8;
    int brow = (mat >> 1) * 8 + lr, bcol = (mat & 1) * 8;

    float acc[4][8][4];
#pragma unroll
    for (int a = 0; a < 4; a++)
#pragma unroll
        for (int b = 0; b < 8; b++)
#pragma unroll
            for (int c = 0; c < 4; c++) acc[a][b][c] = 0.0f;

    const f16* Ag0 = A + (size_t)m0 * HID;
    const f16* Bg0 = B + (size_t)n0 * HID;

    auto loadStage = [&](int s, int kt) {
        uint32_t Ab = sb + s * G_STG;
        uint32_t Bb = Ab + G_ABYTES;
        const f16* Ag = Ag0 + kt * 64;
        const f16* Bg = Bg0 + kt * 64;
#pragma unroll
        for (int u = 0; u < 4; u++) {            // A: 1024 chunks / 256 thr
            int idx = tid + u * 256;
            int r = idx >> 3, c = idx & 7;
            cpa16(Ab + r * 144 + c * 16, Ag + (size_t)r * HID + c * 8);
        }
#pragma unroll
        for (int u = 0; u < 8; u++) {            // B: 2048 chunks / 256 thr
            int idx = tid + u * 256;
            int r = idx >> 3, c = idx & 7;
            cpa16(Bb + r * 144 + c * 16, Bg + (size_t)r * HID + c * 8);
        }
    };

    loadStage(0, 0); cpa_commit();
    loadStage(1, 1); cpa_commit();

    for (int kt = 0; kt < 16; kt++) {
        int s = kt % 3;
        if (kt <= 13) {
            loadStage((kt + 2) % 3, kt + 2);
            cpa_commit();
            cpa_wait<2>();
        } else if (kt == 14) {
            cpa_wait<1>();
        } else {
            cpa_wait<0>();
        }
        __syncthreads();

        uint32_t Ab = sb + s * G_STG;
        uint32_t Bb = Ab + G_ABYTES;
#pragma unroll
        for (int ks = 0; ks < 4; ks++) {
            uint32_t a[4][4];
#pragma unroll
            for (int mt = 0; mt < 4; mt++)
                ldm4(a[mt][0], a[mt][1], a[mt][2], a[mt][3],
                     Ab + (wm + mt * 16 + arow) * 144 + (ks * 16 + acol) * 2);
#pragma unroll
            for (int nb = 0; nb < 4; nb++) {
                uint32_t b0, b1, b2, b3;
                ldm4(b0, b1, b2, b3,
                     Bb + (wn + nb * 16 + brow) * 144 + (ks * 16 + bcol) * 2);
#pragma unroll
                for (int mt = 0; mt < 4; mt++) {
                    mma16816(acc[mt][nb * 2 + 0], a[mt][0], a[mt][1], a[mt][2], a[mt][3], b0, b1);
                    mma16816(acc[mt][nb * 2 + 1], a[mt][0], a[mt][1], a[mt][2], a[mt][3], b2, b3);
                }
            }
        }
        __syncthreads();
    }

    int g = lane >> 2, t2 = lane & 3;
#pragma unroll
    for (int np = 0; np < 8; np++) {
        int col = n0 + wn + np * 8 + t2 * 2;
        float2 bv = *(const float2*)&bias[col];
#pragma unroll
        for (int mt = 0; mt < 4; mt++)
#pragma unroll
            for (int hh = 0; hh < 2; hh++) {
                int row = m0 + wm + mt * 16 + g + hh * 8;
                float2 v;
                v.x = acc[mt][np][hh * 2 + 0] + bv.x;
                v.y = acc[mt][np][hh * 2 + 1] + bv.y;
                *(float2*)&C[(size_t)row * ldc + col] = v;
            }
    }
}

// ---- recurrence init ----
__global__ void rec_init_k(const float* __restrict__ h0l) {
    int i = blockIdx.x * blockDim.x + threadIdx.x;
    if (i == 0) { g_bar_arrive = 0; g_bar_gen = 0; }
    if (i < BATCH * HID) g_hbuf[0][i] = __float2half(h0l[i]);
}

// ---- persistent LSTM recurrence (unchanged, proven) ----
#define REC_NCTA 64
#define WPITCH 1032
#define REC_SMEM ((64 * WPITCH + 32 * WPITCH) * 2 + 64 * 32 * 4)

__global__ __launch_bounds__(256) void lstm_rec_k(
    const f16* __restrict__ whh, const float* __restrict__ gin,
    const float* __restrict__ c0l, f16* __restrict__ ybuf,
    float* __restrict__ outH, float* __restrict__ outC) {
    extern __shared__ char smem_raw[];
    f16* WS = (f16*)smem_raw;
    f16* HS = WS + 64 * WPITCH;
    float* STAGE = (float*)(HS + 32 * WPITCH);

    int tid = threadIdx.x, lane = tid & 31, warp = tid >> 5;
    int cta = blockIdx.x, j0 = cta * 16;

    for (int u = tid; u < 64 * 128; u += 256) {
        int r = u >> 7, c = (u & 127) * 8;
        int q = r >> 4, jl = r & 15;
        *(uint4*)&WS[r * WPITCH + c] =
            *(const uint4*)&whh[(size_t)(q * HID + j0 + jl) * HID + c];
    }
    int p0 = tid * 2, p1 = tid * 2 + 1;
    int b0e = p0 >> 4, j0e = p0 & 15;
    int b1e = p1 >> 4, j1e = p1 & 15;
    float cst0 = c0l[b0e * HID + j0 + j0e];
    float cst1 = c0l[b1e * HID + j0 + j1e];

    int mt = warp & 3, ntp = warp >> 2;
    int mat = lane >> 3, lr = lane & 7;
    uint32_t aBase = smaddr(&WS[(mt * 16 + (mat & 1) * 8 + lr) * WPITCH + (mat >> 1) * 8]);
    uint32_t bBase = smaddr(&HS[(ntp * 16 + (mat >> 1) * 8 + lr) * WPITCH + (mat & 1) * 8]);

    __syncthreads();
    unsigned gen = 0;

    for (int t = 0; t < SEQ; t++) {
        float gi0[4], gi1[4];
        const float* gp0 = gin + (size_t)(t * BATCH + b0e) * GATES + (j0 + j0e);
        const float* gp1 = gin + (size_t)(t * BATCH + b1e) * GATES + (j0 + j1e);
#pragma unroll
        for (int q = 0; q < 4; q++) { gi0[q] = gp0[q * HID]; gi1[q] = gp1[q * HID]; }

        const uint4* hsrc = (const uint4*)g_hbuf[t & 1];
        for (int u = tid; u < 4096; u += 256) {
            int b = u >> 7, c = (u & 127) * 8;
            *(uint4*)&HS[b * WPITCH + c] = hsrc[u];
        }
        __syncthreads();

        float acc0[4] = {0, 0, 0, 0}, acc1[4] = {0, 0, 0, 0};
#pragma unroll 4
        for (int kc = 0; kc < 64; kc++) {
            uint32_t a0, a1, a2, a3, b0, b1, b2, b3;
            ldm4(a0, a1, a2, a3, aBase + kc * 32);
            ldm4(b0, b1, b2, b3, bBase + kc * 32);
            mma16816(acc0, a0, a1, a2, a3, b0, b1);
            mma16816(acc1, a0, a1, a2, a3, b2, b3);
        }
        {
            int g = lane >> 2, t2 = lane & 3;
#pragma unroll
            for (int i = 0; i < 4; i++) {
                int r = mt * 16 + g + (i >> 1) * 8;
                STAGE[r * 32 + ntp * 16 + t2 * 2 + (i & 1)] = acc0[i];
                STAGE[r * 32 + ntp * 16 + 8 + t2 * 2 + (i & 1)] = acc1[i];
            }
        }
        __syncthreads();

        f16* hnew = g_hbuf[(t + 1) & 1];
        {
            float iv = STAGE[(j0e) * 32 + b0e] + gi0[0];
            float fv = STAGE[(16 + j0e) * 32 + b0e] + gi0[1];
            float gv = STAGE[(32 + j0e) * 32 + b0e] + gi0[2];
            float ov = STAGE[(48 + j0e) * 32 + b0e] + gi0[3];
            float cn = sigmf(fv) * cst0 + sigmf(iv) * tanhf(gv);
            float hn = sigmf(ov) * tanhf(cn);
            cst0 = cn;
            f16 hb = __float2half(hn);
            hnew[b0e * HID + j0 + j0e] = hb;
            ybuf[(size_t)(t * BATCH + b0e) * HID + j0 + j0e] = hb;
            if (t == SEQ - 1) { outH[b0e * HID + j0 + j0e] = hn; outC[b0e * HID + j0 + j0e] = cn; }
        }
        {
            float iv = STAGE[(j1e) * 32 + b1e] + gi1[0];
            float fv = STAGE[(16 + j1e) * 32 + b1e] + gi1[1];
            float gv = STAGE[(32 + j1e) * 32 + b1e] + gi1[2];
            float ov = STAGE[(48 + j1e) * 32 + b1e] + gi1[3];
            float cn = sigmf(fv) * cst1 + sigmf(iv) * tanhf(gv);
            float hn = sigmf(ov) * tanhf(cn);
            cst1 = cn;
            f16 hb = __float2half(hn);
            hnew[b1e * HID + j0 + j1e] = hb;
            ybuf[(size_t)(t * BATCH + b1e) * HID + j0 + j1e] = hb;
            if (t == SEQ - 1) { outH[b1e * HID + j0 + j1e] = hn; outC[b1e * HID + j0 + j1e] = cn; }
        }
        __syncthreads();
        if (tid == 0) {
            __threadfence();
            gen++;
            unsigned old = atomicAdd(&g_bar_arrive, 1);
            if (old == REC_NCTA - 1) {
                g_bar_arrive = 0;
                __threadfence();
                g_bar_gen = gen;
            } else {
                while (g_bar_gen < gen) {}
            }
            __threadfence();
        }
        __syncthreads();
    }
}

// ---- fused log_softmax: one 32000-f32 row per CTA (1024 threads) ----
#define SMT 1024
__global__ __launch_bounds__(SMT) void softmax_k(float* __restrict__ out) {
    extern __shared__ float row[];
    __shared__ float red[32];
    int tid = threadIdx.x;
    float* dst = out + (size_t)blockIdx.x * VOCAB;
    float4* s4 = (float4*)row;
    float4* g4 = (float4*)dst;

    float lmax = -1e30f;
    for (int i = tid; i < VOCAB / 4; i += SMT) {
        float4 v = g4[i];
        s4[i] = v;
        lmax = fmaxf(lmax, fmaxf(fmaxf(v.x, v.y), fmaxf(v.z, v.w)));
    }
#pragma unroll
    for (int o = 16; o; o >>= 1) lmax = fmaxf(lmax, __shfl_xor_sync(~0u, lmax, o));
    if ((tid & 31) == 0) red[tid >> 5] = lmax;
    __syncthreads();
    float bmax = red[0];
#pragma unroll
    for (int w = 1; w < 32; w++) bmax = fmaxf(bmax, red[w]);

    float lsum = 0.0f;
    for (int i = tid; i < VOCAB / 4; i += SMT) {
        float4 v = s4[i];
        lsum += __expf(v.x - bmax) + __expf(v.y - bmax) +
                __expf(v.z - bmax) + __expf(v.w - bmax);
    }
#pragma unroll
    for (int o = 16; o; o >>= 1) lsum += __shfl_xor_sync(~0u, lsum, o);
    __syncthreads();
    if ((tid & 31) == 0) red[tid >> 5] = lsum;
    __syncthreads();
    float bsum = red[0];
#pragma unroll
    for (int w = 1; w < 32; w++) bsum += red[w];

    float lse = bmax + logf(bsum);
    for (int i = tid; i < VOCAB / 4; i += SMT) {
        float4 v = s4[i];
        v.x -= lse; v.y -= lse; v.z -= lse; v.w -= lse;
        g4[i] = v;
    }
}

// ---- host orchestration (graph-capturable) ----
extern "C" void kernel_launch(void* const* d_in, const int* in_sizes, int n_in,
                              void* d_out, int out_size) {
    (void)in_sizes; (void)n_in; (void)out_size;
    const int*   tokens = (const int*)d_in[0];
    const float* h0     = (const float*)d_in[1];
    const float* c0     = (const float*)d_in[2];
    const float* emb    = (const float*)d_in[3];
    const float* w_ih   = (const float*)d_in[4];
    const float* w_hh   = (const float*)d_in[5];
    const float* b_ih   = (const float*)d_in[6];
    const float* b_hh   = (const float*)d_in[7];
    const float* w_dec  = (const float*)d_in[8];
    const float* b_dec  = (const float*)d_in[9];

    float* out  = (float*)d_out;
    float* outH = out + (size_t)M_TOT * VOCAB;
    float* outC = outH + (size_t)NLAYER * BATCH * HID;

    f16 *wihH, *whhH, *wdecH, *xa, *xb;
    float *biasC, *gbuf;
    cudaGetSymbolAddress((void**)&wihH, g_wihH);
    cudaGetSymbolAddress((void**)&whhH, g_whhH);
    cudaGetSymbolAddress((void**)&wdecH, g_wdecH);
    cudaGetSymbolAddress((void**)&biasC, g_biasC);
    cudaGetSymbolAddress((void**)&xa, g_xa);
    cudaGetSymbolAddress((void**)&xb, g_xb);
    cudaGetSymbolAddress((void**)&gbuf, g_gates);

    cudaFuncSetAttribute(lstm_rec_k, cudaFuncAttributeMaxDynamicSharedMemorySize, REC_SMEM);
    cudaFuncSetAttribute(softmax_k, cudaFuncAttributeMaxDynamicSharedMemorySize, VOCAB * 4);
    cudaFuncSetAttribute(gemm_nt_k, cudaFuncAttributeMaxDynamicSharedMemorySize, GEMM_SMEM);

    f2h_k<<<2048, 256>>>(w_ih, wihH, 2L * GATES * HID);
    f2h_k<<<2048, 256>>>(w_hh, whhH, 2L * GATES * HID);
    f2h_k<<<4096, 256>>>(w_dec, wdecH, (long)VOCAB * HID);
    bias_k<<<32, 256>>>(b_ih, b_hh, biasC, 2 * GATES);
    embed_k<<<M_TOT, 256>>>(tokens, emb, xa);

    for (int l = 0; l < NLAYER; l++) {
        const f16* Ain = l ? xb : xa;
        f16* Yout      = l ? xa : xb;
        gemm_nt_k<<<dim3(GATES / 256, M_TOT / 128), 256, GEMM_SMEM>>>(
            Ain, wihH + (size_t)l * GATES * HID, biasC + l * GATES, gbuf, GATES);
        rec_init_k<<<(BATCH * HID + 255) / 256, 256>>>(h0 + (size_t)l * BATCH * HID);
        lstm_rec_k<<<REC_NCTA, 256, REC_SMEM>>>(
            whhH + (size_t)l * GATES * HID, gbuf, c0 + (size_t)l * BATCH * HID,
            Yout, outH + (size_t)l * BATCH * HID, outC + (size_t)l * BATCH * HID);
    }
    gemm_nt_k<<<dim3(VOCAB / 256, M_TOT / 128), 256, GEMM_SMEM>>>(
        xa, wdecH, b_dec, out, VOCAB);
    softmax_k<<<M_TOT, SMT, VOCAB * 4>>>(out);
}

// round 17
// speedup vs baseline: 1.1065x; 1.1065x over previous
#include <cuda_runtime.h>
#include <cuda_fp16.h>
#include <cstdint>

using f16 = __half;
#define DINLINE __device__ __forceinline__

#define SEQ 128
#define BATCH 32
#define VOCAB 32000
#define HID 1024
#define NLAYER 2
#define M_TOT (SEQ * BATCH)   // 4096
#define GATES (4 * HID)       // 4096

// ---- static device scratch ----
__device__ f16   g_wihH[2ull * GATES * HID];
__device__ f16   g_whhH[2ull * GATES * HID];
__device__ f16   g_wdecH[(size_t)VOCAB * HID];
__device__ float g_biasC[2 * GATES];
__device__ f16   g_xa[(size_t)M_TOT * HID];
__device__ f16   g_xb[(size_t)M_TOT * HID];
__device__ float g_gates[(size_t)M_TOT * GATES];
__device__ f16   g_hbuf[2][BATCH * HID];
__device__ volatile int g_flags[64 * 32];   // one flag per CTA, 128B apart

DINLINE uint32_t smaddr(const void* p) { return (uint32_t)__cvta_generic_to_shared(p); }
DINLINE void ldm4(uint32_t& r0, uint32_t& r1, uint32_t& r2, uint32_t& r3, uint32_t a) {
    asm volatile("ldmatrix.sync.aligned.m8n8.x4.shared.b16 {%0,%1,%2,%3}, [%4];"
                 : "=r"(r0), "=r"(r1), "=r"(r2), "=r"(r3) : "r"(a));
}
DINLINE void mma16816(float* c, uint32_t a0, uint32_t a1, uint32_t a2, uint32_t a3,
                      uint32_t b0, uint32_t b1) {
    asm volatile("mma.sync.aligned.m16n8k16.row.col.f32.f16.f16.f32 "
                 "{%0,%1,%2,%3}, {%4,%5,%6,%7}, {%8,%9}, {%0,%1,%2,%3};"
                 : "+f"(c[0]), "+f"(c[1]), "+f"(c[2]), "+f"(c[3])
                 : "r"(a0), "r"(a1), "r"(a2), "r"(a3), "r"(b0), "r"(b1));
}
DINLINE void cpa16(uint32_t s, const void* g) {
    asm volatile("cp.async.cg.shared.global [%0], [%1], 16;" :: "r"(s), "l"(g));
}
DINLINE void cpa_commit() { asm volatile("cp.async.commit_group;"); }
template <int N> DINLINE void cpa_wait() { asm volatile("cp.async.wait_group %0;" :: "n"(N)); }
DINLINE float sigmf(float x) { return 1.0f / (1.0f + __expf(-x)); }

// ---- fp32 -> fp16 convert ----
__global__ void f2h_k(const float* __restrict__ s, f16* __restrict__ d, long n) {
    long i = ((long)blockIdx.x * blockDim.x + threadIdx.x) * 4;
    long st = (long)gridDim.x * blockDim.x * 4;
    for (; i < n; i += st) {
        float4 v = *(const float4*)(s + i);
        __half2* o = (__half2*)(d + i);
        o[0] = __floats2half2_rn(v.x, v.y);
        o[1] = __floats2half2_rn(v.z, v.w);
    }
}
__global__ void bias_k(const float* __restrict__ a, const float* __restrict__ b,
                       float* __restrict__ o, int n) {
    int i = blockIdx.x * blockDim.x + threadIdx.x;
    if (i < n) o[i] = a[i] + b[i];
}
__global__ void embed_k(const int* __restrict__ tok, const float* __restrict__ emb,
                        f16* __restrict__ x) {
    int m = blockIdx.x;
    const float4* s = (const float4*)(emb + (size_t)tok[m] * HID);
    __half2* o = (__half2*)(x + (size_t)m * HID);
    float4 v = s[threadIdx.x];
    o[threadIdx.x * 2 + 0] = __floats2half2_rn(v.x, v.y);
    o[threadIdx.x * 2 + 1] = __floats2half2_rn(v.z, v.w);
}

// ---- NT GEMM (round-13 proven): 128x128 tile, 8 warps (4m x 2n), warp 32x64,
// BK=64, 2-stage cp.async pipeline, pitch-72 SMEM ----
#define GPITCH 72
#define GSTAGE (128 * GPITCH)
#define GEMM_SMEM (4 * GSTAGE * 2)

__global__ __launch_bounds__(256) void gemm_nt_k(
    const f16* __restrict__ A, const f16* __restrict__ B,
    const float* __restrict__ bias, float* __restrict__ C, long ldc) {
    extern __shared__ f16 sm[];
    f16* Abuf = sm;
    f16* Bbuf = sm + 2 * GSTAGE;

    int tid = threadIdx.x, lane = tid & 31, warp = tid >> 5;
    int m0 = blockIdx.y * 128, n0 = blockIdx.x * 128;
    int wm = (warp & 3) * 32, wn = (warp >> 2) * 64;
    int mat = lane >> 3, lr = lane & 7;

    float acc[2][8][4];
#pragma unroll
    for (int a = 0; a < 2; a++)
#pragma unroll
        for (int b = 0; b < 8; b++)
#pragma unroll
            for (int c = 0; c < 4; c++) acc[a][b][c] = 0.0f;

    auto load_stage = [&](int s, int k0) {
        f16* Ap = Abuf + s * GSTAGE;
        f16* Bp = Bbuf + s * GSTAGE;
#pragma unroll
        for (int u = 0; u < 4; u++) {
            int idx = tid + u * 256;
            int row = idx >> 3, col = (idx & 7) * 8;
            cpa16(smaddr(&Ap[row * GPITCH + col]), &A[(size_t)(m0 + row) * HID + k0 + col]);
            cpa16(smaddr(&Bp[row * GPITCH + col]), &B[(size_t)(n0 + row) * HID + k0 + col]);
        }
    };

    load_stage(0, 0);
    cpa_commit();

    const int KT = HID / 64;  // 16
    for (int kt = 0; kt < KT; kt++) {
        int s = kt & 1;
        if (kt + 1 < KT) {
            load_stage(s ^ 1, (kt + 1) * 64);
            cpa_commit();
            cpa_wait<1>();
        } else {
            cpa_wait<0>();
        }
        __syncthreads();

        f16* Ap = Abuf + s * GSTAGE;
        f16* Bp = Bbuf + s * GSTAGE;
#pragma unroll
        for (int ks = 0; ks < 4; ks++) {
            uint32_t a[2][4];
#pragma unroll
            for (int mt = 0; mt < 2; mt++) {
                int r = wm + mt * 16 + (mat & 1) * 8 + lr;
                int cc = ks * 16 + (mat >> 1) * 8;
                ldm4(a[mt][0], a[mt][1], a[mt][2], a[mt][3], smaddr(&Ap[r * GPITCH + cc]));
            }
#pragma unroll
            for (int p = 0; p < 4; p++) {
                uint32_t b0, b1, b2, b3;
                int r = wn + (p * 2 + (mat >> 1)) * 8 + lr;
                int cc = ks * 16 + (mat & 1) * 8;
                ldm4(b0, b1, b2, b3, smaddr(&Bp[r * GPITCH + cc]));
#pragma unroll
                for (int mt = 0; mt < 2; mt++) {
                    mma16816(acc[mt][p * 2 + 0], a[mt][0], a[mt][1], a[mt][2], a[mt][3], b0, b1);
                    mma16816(acc[mt][p * 2 + 1], a[mt][0], a[mt][1], a[mt][2], a[mt][3], b2, b3);
                }
            }
        }
        __syncthreads();
    }

    int g = lane >> 2, t2 = lane & 3;
#pragma unroll
    for (int j = 0; j < 8; j++) {
        int col = n0 + wn + j * 8 + t2 * 2;
        float2 bv = *(const float2*)&bias[col];
#pragma unroll
        for (int mt = 0; mt < 2; mt++)
#pragma unroll
            for (int hh = 0; hh < 2; hh++) {
                int row = m0 + wm + mt * 16 + g + hh * 8;
                float2 v;
                v.x = acc[mt][j][hh * 2 + 0] + bv.x;
                v.y = acc[mt][j][hh * 2 + 1] + bv.y;
                *(float2*)&C[(size_t)row * ldc + col] = v;
            }
    }
}

// ---- recurrence init: reset flags + h(0) ----
__global__ void rec_init_k(const float* __restrict__ h0l) {
    int i = blockIdx.x * blockDim.x + threadIdx.x;
    if (i < 64 * 32) g_flags[i] = 0;
    if (i < BATCH * HID) g_hbuf[0][i] = __float2half(h0l[i]);
}

// ---- persistent LSTM recurrence: 64 CTAs x 256 thr, W slice resident in SMEM.
// v2fix: flag-array barrier + chunked cp.async h staging (4 x 1024 transfers). ----
#define REC_NCTA 64
#define WPITCH 1032
#define REC_SMEM ((64 * WPITCH + 32 * WPITCH) * 2 + 64 * 32 * 4)

__global__ __launch_bounds__(256) void lstm_rec_k(
    const f16* __restrict__ whh, const float* __restrict__ gin,
    const float* __restrict__ c0l, f16* __restrict__ ybuf,
    float* __restrict__ outH, float* __restrict__ outC) {
    extern __shared__ char smem_raw[];
    f16* WS = (f16*)smem_raw;                   // [64][1032]
    f16* HS = WS + 64 * WPITCH;                 // [32][1032]
    float* STAGE = (float*)(HS + 32 * WPITCH);  // [64][32]

    int tid = threadIdx.x, lane = tid & 31, warp = tid >> 5;
    int cta = blockIdx.x, j0 = cta * 16;

    for (int u = tid; u < 64 * 128; u += 256) {
        int r = u >> 7, c = (u & 127) * 8;
        int q = r >> 4, jl = r & 15;
        *(uint4*)&WS[r * WPITCH + c] =
            *(const uint4*)&whh[(size_t)(q * HID + j0 + jl) * HID + c];
    }
    int p0 = tid * 2, p1 = tid * 2 + 1;
    int b0e = p0 >> 4, j0e = p0 & 15;
    int b1e = p1 >> 4, j1e = p1 & 15;
    float cst0 = c0l[b0e * HID + j0 + j0e];
    float cst1 = c0l[b1e * HID + j0 + j1e];

    int mt = warp & 3, ntp = warp >> 2;
    int mat = lane >> 3, lr = lane & 7;
    uint32_t aBase = smaddr(&WS[(mt * 16 + (mat & 1) * 8 + lr) * WPITCH + (mat >> 1) * 8]);
    uint32_t bBase = smaddr(&HS[(ntp * 16 + (mat >> 1) * 8 + lr) * WPITCH + (mat & 1) * 8]);
    uint32_t hsBase = smaddr(HS);

    __syncthreads();

    for (int t = 0; t < SEQ; t++) {
        // prefetch input preactivations (independent of h)
        float gi0[4], gi1[4];
        const float* gp0 = gin + (size_t)(t * BATCH + b0e) * GATES + (j0 + j0e);
        const float* gp1 = gin + (size_t)(t * BATCH + b1e) * GATES + (j0 + j1e);
#pragma unroll
        for (int q = 0; q < 4; q++) { gi0[q] = gp0[q * HID]; gi1[q] = gp1[q * HID]; }

        // stage h(t) into SMEM as 4 K-chunks; each chunk = 512B x 32 rows
        // = 1024 x 16B cp.async transfers (4 per thread).
        const char* hsrc = (const char*)g_hbuf[t & 1];
#pragma unroll
        for (int c = 0; c < 4; c++) {
#pragma unroll
            for (int v = 0; v < 4; v++) {
                int u = tid + v * 256;            // 1024 transfers
                int r = u >> 5, cc = u & 31;
                cpa16(hsBase + r * (WPITCH * 2) + c * 512 + cc * 16,
                      hsrc + r * 2048 + c * 512 + cc * 16);
            }
            cpa_commit();
        }

        float acc0[4] = {0, 0, 0, 0}, acc1[4] = {0, 0, 0, 0};
#pragma unroll
        for (int c = 0; c < 4; c++) {
            if (c == 0) cpa_wait<3>();
            else if (c == 1) cpa_wait<2>();
            else if (c == 2) cpa_wait<1>();
            else cpa_wait<0>();
            __syncthreads();
#pragma unroll
            for (int kc = c * 16; kc < c * 16 + 16; kc++) {
                uint32_t a0, a1, a2, a3, b0, b1, b2, b3;
                ldm4(a0, a1, a2, a3, aBase + kc * 32);
                ldm4(b0, b1, b2, b3, bBase + kc * 32);
                mma16816(acc0, a0, a1, a2, a3, b0, b1);
                mma16816(acc1, a0, a1, a2, a3, b2, b3);
            }
        }
        {
            int g = lane >> 2, t2 = lane & 3;
#pragma unroll
            for (int i = 0; i < 4; i++) {
                int r = mt * 16 + g + (i >> 1) * 8;
                STAGE[r * 32 + ntp * 16 + t2 * 2 + (i & 1)] = acc0[i];
                STAGE[r * 32 + ntp * 16 + 8 + t2 * 2 + (i & 1)] = acc1[i];
            }
        }
        __syncthreads();

        f16* hnew = g_hbuf[(t + 1) & 1];
        {
            float iv = STAGE[(j0e) * 32 + b0e] + gi0[0];
            float fv = STAGE[(16 + j0e) * 32 + b0e] + gi0[1];
            float gv = STAGE[(32 + j0e) * 32 + b0e] + gi0[2];
            float ov = STAGE[(48 + j0e) * 32 + b0e] + gi0[3];
            float cn = sigmf(fv) * cst0 + sigmf(iv) * tanhf(gv);
            float hn = sigmf(ov) * tanhf(cn);
            cst0 = cn;
            f16 hb = __float2half(hn);
            hnew[b0e * HID + j0 + j0e] = hb;
            ybuf[(size_t)(t * BATCH + b0e) * HID + j0 + j0e] = hb;
            if (t == SEQ - 1) { outH[b0e * HID + j0 + j0e] = hn; outC[b0e * HID + j0 + j0e] = cn; }
        }
        {
            float iv = STAGE[(j1e) * 32 + b1e] + gi1[0];
            float fv = STAGE[(16 + j1e) * 32 + b1e] + gi1[1];
            float gv = STAGE[(32 + j1e) * 32 + b1e] + gi1[2];
            float ov = STAGE[(48 + j1e) * 32 + b1e] + gi1[3];
            float cn = sigmf(fv) * cst1 + sigmf(iv) * tanhf(gv);
            float hn = sigmf(ov) * tanhf(cn);
            cst1 = cn;
            f16 hb = __float2half(hn);
            hnew[b1e * HID + j0 + j1e] = hb;
            ybuf[(size_t)(t * BATCH + b1e) * HID + j0 + j1e] = hb;
            if (t == SEQ - 1) { outH[b1e * HID + j0 + j1e] = hn; outC[b1e * HID + j0 + j1e] = cn; }
        }
        // flag-array barrier: per-CTA flag, warp 0 polls all 64
        __threadfence();
        __syncthreads();
        if (tid == 0) g_flags[cta * 32] = t + 1;
        if (warp == 0) {
            int f1, f2;
            do {
                f1 = g_flags[lane * 32];
                f2 = g_flags[(lane + 32) * 32];
            } while (__any_sync(~0u, (f1 <= t) || (f2 <= t)));
        }
        __syncthreads();
        __threadfence();
    }
}

// ---- fused log_softmax: one 32000-f32 row per CTA (1024 threads) ----
#define SMT 1024
__global__ __launch_bounds__(SMT) void softmax_k(float* __restrict__ out) {
    extern __shared__ float row[];
    __shared__ float red[32];
    int tid = threadIdx.x;
    float* dst = out + (size_t)blockIdx.x * VOCAB;
    float4* s4 = (float4*)row;
    float4* g4 = (float4*)dst;

    float lmax = -1e30f;
    for (int i = tid; i < VOCAB / 4; i += SMT) {
        float4 v = g4[i];
        s4[i] = v;
        lmax = fmaxf(lmax, fmaxf(fmaxf(v.x, v.y), fmaxf(v.z, v.w)));
    }
#pragma unroll
    for (int o = 16; o; o >>= 1) lmax = fmaxf(lmax, __shfl_xor_sync(~0u, lmax, o));
    if ((tid & 31) == 0) red[tid >> 5] = lmax;
    __syncthreads();
    float bmax = red[0];
#pragma unroll
    for (int w = 1; w < 32; w++) bmax = fmaxf(bmax, red[w]);

    float lsum = 0.0f;
    for (int i = tid; i < VOCAB / 4; i += SMT) {
        float4 v = s4[i];
        lsum += __expf(v.x - bmax) + __expf(v.y - bmax) +
                __expf(v.z - bmax) + __expf(v.w - bmax);
    }
#pragma unroll
    for (int o = 16; o; o >>= 1) lsum += __shfl_xor_sync(~0u, lsum, o);
    __syncthreads();
    if ((tid & 31) == 0) red[tid >> 5] = lsum;
    __syncthreads();
    float bsum = red[0];
#pragma unroll
    for (int w = 1; w < 32; w++) bsum += red[w];

    float lse = bmax + logf(bsum);
    for (int i = tid; i < VOCAB / 4; i += SMT) {
        float4 v = s4[i];
        v.x -= lse; v.y -= lse; v.z -= lse; v.w -= lse;
        g4[i] = v;
    }
}

// ---- host orchestration (graph-capturable) ----
extern "C" void kernel_launch(void* const* d_in, const int* in_sizes, int n_in,
                              void* d_out, int out_size) {
    (void)in_sizes; (void)n_in; (void)out_size;
    const int*   tokens = (const int*)d_in[0];
    const float* h0     = (const float*)d_in[1];
    const float* c0     = (const float*)d_in[2];
    const float* emb    = (const float*)d_in[3];
    const float* w_ih   = (const float*)d_in[4];
    const float* w_hh   = (const float*)d_in[5];
    const float* b_ih   = (const float*)d_in[6];
    const float* b_hh   = (const float*)d_in[7];
    const float* w_dec  = (const float*)d_in[8];
    const float* b_dec  = (const float*)d_in[9];

    float* out  = (float*)d_out;
    float* outH = out + (size_t)M_TOT * VOCAB;
    float* outC = outH + (size_t)NLAYER * BATCH * HID;

    f16 *wihH, *whhH, *wdecH, *xa, *xb;
    float *biasC, *gbuf;
    cudaGetSymbolAddress((void**)&wihH, g_wihH);
    cudaGetSymbolAddress((void**)&whhH, g_whhH);
    cudaGetSymbolAddress((void**)&wdecH, g_wdecH);
    cudaGetSymbolAddress((void**)&biasC, g_biasC);
    cudaGetSymbolAddress((void**)&xa, g_xa);
    cudaGetSymbolAddress((void**)&xb, g_xb);
    cudaGetSymbolAddress((void**)&gbuf, g_gates);

    cudaFuncSetAttribute(lstm_rec_k, cudaFuncAttributeMaxDynamicSharedMemorySize, REC_SMEM);
    cudaFuncSetAttribute(softmax_k, cudaFuncAttributeMaxDynamicSharedMemorySize, VOCAB * 4);
    cudaFuncSetAttribute(gemm_nt_k, cudaFuncAttributeMaxDynamicSharedMemorySize, GEMM_SMEM);

    f2h_k<<<2048, 256>>>(w_ih, wihH, 2L * GATES * HID);
    f2h_k<<<2048, 256>>>(w_hh, whhH, 2L * GATES * HID);
    f2h_k<<<4096, 256>>>(w_dec, wdecH, (long)VOCAB * HID);
    bias_k<<<32, 256>>>(b_ih, b_hh, biasC, 2 * GATES);
    embed_k<<<M_TOT, 256>>>(tokens, emb, xa);

    for (int l = 0; l < NLAYER; l++) {
        const f16* Ain = l ? xb : xa;
        f16* Yout      = l ? xa : xb;
        gemm_nt_k<<<dim3(GATES / 128, M_TOT / 128), 256, GEMM_SMEM>>>(
            Ain, wihH + (size_t)l * GATES * HID, biasC + l * GATES, gbuf, GATES);
        rec_init_k<<<(BATCH * HID + 255) / 256, 256>>>(h0 + (size_t)l * BATCH * HID);
        lstm_rec_k<<<REC_NCTA, 256, REC_SMEM>>>(
            whhH + (size_t)l * GATES * HID, gbuf, c0 + (size_t)l * BATCH * HID,
            Yout, outH + (size_t)l * BATCH * HID, outC + (size_t)l * BATCH * HID);
    }
    gemm_nt_k<<<dim3(VOCAB / 128, M_TOT / 128), 256, GEMM_SMEM>>>(
        xa, wdecH, b_dec, out, VOCAB);
    softmax_k<<<M_TOT, SMT, VOCAB * 4>>>(out);
}